// round 1
// baseline (speedup 1.0000x reference)
#include <cuda_runtime.h>
#include <math.h>
#include <float.h>

// Problem: B=256 queries x N=500000 embeddings, D=768, top-17 cosine sim.
#define DDIM 768
#define KSEL 17          // k+1 = 17
#define BQ   256         // queries (CTA covers all of them)
#define TILE_N 64        // embedding rows per CTA
#define KC 16            // K-chunk

// Scratch (allocation-free rule: __device__ globals)
__device__ float g_scores[256u * 500000u];   // 512 MB score matrix [q][n]
__device__ float g_invq[BQ];

// ---------------------------------------------------------------------------
// Kernel 1: per-query inverse norms (one warp per row)
// ---------------------------------------------------------------------------
__global__ void qnorm_kernel(const float* __restrict__ Q, int B) {
    int warp = (blockIdx.x * blockDim.x + threadIdx.x) >> 5;
    int lane = threadIdx.x & 31;
    if (warp >= B) return;
    const float4* row = (const float4*)(Q + (size_t)warp * DDIM);
    float s = 0.f;
    #pragma unroll 2
    for (int i = lane; i < DDIM / 4; i += 32) {
        float4 v = row[i];
        s += v.x * v.x + v.y * v.y + v.z * v.z + v.w * v.w;
    }
    #pragma unroll
    for (int o = 16; o; o >>= 1) s += __shfl_xor_sync(0xFFFFFFFFu, s, o);
    if (lane == 0) g_invq[warp] = 1.0f / sqrtf(s);
}

// ---------------------------------------------------------------------------
// Kernel 2: fp32 GEMM tile 256q x 64e, K=768 in chunks of 16.
// Embedding-row inverse norms are computed on the fly from the same loads
// (embeddings are read exactly once from HBM).
// ---------------------------------------------------------------------------
__global__ __launch_bounds__(256, 2)
void gemm_kernel(const float* __restrict__ Q, const float* __restrict__ E, int N) {
    __shared__ float Qs[KC][BQ];        // [k][q]
    __shared__ float Es[KC][TILE_N + 4];// [k][e], padded stride 68 (16B-aligned rows)
    __shared__ float s_inve[TILE_N];

    const int tid   = threadIdx.x;
    const int nbase = blockIdx.x * TILE_N;
    const int qt = tid >> 4;   // 0..15  -> query group (16 queries each)
    const int et = tid & 15;   // 0..15  -> embedding group (4 rows each)

    // E-load mapping: each thread owns one embedding row slice across all chunks
    const int er = tid >> 2;   // 0..63 row within tile
    const int eq = tid & 3;    // 0..3  quarter of the 16-wide k-chunk
    const bool evalid = (nbase + er) < N;
    const float4* Erow = evalid ? (const float4*)(E + (size_t)(nbase + er) * DDIM)
                                : (const float4*)E;

    float acc[16][4];
    #pragma unroll
    for (int i = 0; i < 16; i++)
        #pragma unroll
        for (int j = 0; j < 4; j++) acc[i][j] = 0.f;

    float esq = 0.f;

    const float4* Qrow = (const float4*)(Q + (size_t)tid * DDIM);

    for (int kb = 0; kb < DDIM; kb += KC) {
        // stage global loads in registers
        float4 qv[4];
        #pragma unroll
        for (int kk = 0; kk < 4; kk++) qv[kk] = Qrow[(kb >> 2) + kk];
        float4 ev = make_float4(0.f, 0.f, 0.f, 0.f);
        if (evalid) ev = Erow[(kb >> 2) + eq];

        __syncthreads();   // previous chunk fully consumed
        #pragma unroll
        for (int kk = 0; kk < 4; kk++) {
            Qs[kk * 4 + 0][tid] = qv[kk].x;
            Qs[kk * 4 + 1][tid] = qv[kk].y;
            Qs[kk * 4 + 2][tid] = qv[kk].z;
            Qs[kk * 4 + 3][tid] = qv[kk].w;
        }
        Es[eq * 4 + 0][er] = ev.x;
        Es[eq * 4 + 1][er] = ev.y;
        Es[eq * 4 + 2][er] = ev.z;
        Es[eq * 4 + 3][er] = ev.w;
        esq += ev.x * ev.x + ev.y * ev.y + ev.z * ev.z + ev.w * ev.w;
        __syncthreads();

        #pragma unroll
        for (int k = 0; k < KC; k++) {
            float4 e4 = *(const float4*)&Es[k][et * 4];
            #pragma unroll
            for (int i = 0; i < 4; i++) {
                float4 q4 = *(const float4*)&Qs[k][qt * 16 + i * 4];
                acc[i * 4 + 0][0] += q4.x * e4.x;
                acc[i * 4 + 0][1] += q4.x * e4.y;
                acc[i * 4 + 0][2] += q4.x * e4.z;
                acc[i * 4 + 0][3] += q4.x * e4.w;
                acc[i * 4 + 1][0] += q4.y * e4.x;
                acc[i * 4 + 1][1] += q4.y * e4.y;
                acc[i * 4 + 1][2] += q4.y * e4.z;
                acc[i * 4 + 1][3] += q4.y * e4.w;
                acc[i * 4 + 2][0] += q4.z * e4.x;
                acc[i * 4 + 2][1] += q4.z * e4.y;
                acc[i * 4 + 2][2] += q4.z * e4.z;
                acc[i * 4 + 2][3] += q4.z * e4.w;
                acc[i * 4 + 3][0] += q4.w * e4.x;
                acc[i * 4 + 3][1] += q4.w * e4.y;
                acc[i * 4 + 3][2] += q4.w * e4.z;
                acc[i * 4 + 3][3] += q4.w * e4.w;
            }
        }
    }

    // reduce embedding sum-of-squares across the 4 threads sharing a row
    esq += __shfl_xor_sync(0xFFFFFFFFu, esq, 1);
    esq += __shfl_xor_sync(0xFFFFFFFFu, esq, 2);
    if (eq == 0) s_inve[er] = evalid ? (1.0f / sqrtf(esq)) : 0.f;
    __syncthreads();

    float ie[4];
    #pragma unroll
    for (int j = 0; j < 4; j++) ie[j] = s_inve[et * 4 + j];

    const int n0 = nbase + et * 4;
    #pragma unroll
    for (int i = 0; i < 16; i++) {
        int q = qt * 16 + i;
        float qi = g_invq[q];
        float4 o;
        o.x = acc[i][0] * qi * ie[0];
        o.y = acc[i][1] * qi * ie[1];
        o.z = acc[i][2] * qi * ie[2];
        o.w = acc[i][3] * qi * ie[3];
        if (n0 + 3 < N) {
            *(float4*)&g_scores[(size_t)q * N + n0] = o;
        } else {
            float vv[4] = {o.x, o.y, o.z, o.w};
            for (int j = 0; j < 4; j++)
                if (n0 + j < N) g_scores[(size_t)q * N + n0 + j] = vv[j];
        }
    }
}

// ---------------------------------------------------------------------------
// Kernel 3: per-query top-17 with jax top_k tie-breaking (value desc, then
// index asc). One CTA (256 threads) per query; thread-local sorted insert,
// then tree merge of sorted 17-lists in shared memory.
// ---------------------------------------------------------------------------
__global__ void topk_kernel(float* __restrict__ out, int N, int B, int out_size) {
    const int q = blockIdx.x;
    const float* row = g_scores + (size_t)q * N;

    float lv[KSEL];
    int   li[KSEL];
    #pragma unroll
    for (int j = 0; j < KSEL; j++) { lv[j] = -FLT_MAX; li[j] = 0x7FFFFFFF; }
    float vmin = -FLT_MAX;

    for (int n = threadIdx.x; n < N; n += blockDim.x) {
        float v = row[n];
        if (v > vmin) {   // scan is ascending-n: equal values keep earlier (smaller) index
            int pos = KSEL - 1;
            #pragma unroll
            for (int step = 0; step < KSEL - 1; step++) {
                if (pos > 0 && v > lv[pos - 1]) {
                    lv[pos] = lv[pos - 1];
                    li[pos] = li[pos - 1];
                    pos--;
                }
            }
            lv[pos] = v;
            li[pos] = n;
            vmin = lv[KSEL - 1];
        }
    }

    __shared__ float sv[256 * KSEL];
    __shared__ int   si[256 * KSEL];
    #pragma unroll
    for (int j = 0; j < KSEL; j++) {
        sv[threadIdx.x * KSEL + j] = lv[j];
        si[threadIdx.x * KSEL + j] = li[j];
    }

    // tree merge: 256 sorted lists -> 1
    for (int half = 128; half >= 1; half >>= 1) {
        __syncthreads();
        if (threadIdx.x < half) {
            float* av = &sv[threadIdx.x * KSEL];
            int*   ai = &si[threadIdx.x * KSEL];
            float* bv = &sv[(threadIdx.x + half) * KSEL];
            int*   bi = &si[(threadIdx.x + half) * KSEL];
            float tv[KSEL]; int ti[KSEL];
            int ia = 0, ib = 0;
            #pragma unroll
            for (int j = 0; j < KSEL; j++) {
                float va = av[ia], vb = bv[ib];
                int   xa = ai[ia], xb = bi[ib];
                bool takea = (va > vb) || (va == vb && xa < xb);
                if (takea) { tv[j] = va; ti[j] = xa; ia++; }
                else       { tv[j] = vb; ti[j] = xb; ib++; }
            }
            #pragma unroll
            for (int j = 0; j < KSEL; j++) { av[j] = tv[j]; ai[j] = ti[j]; }
        }
    }
    __syncthreads();

    if (threadIdx.x < KSEL) {
        out[q * KSEL + threadIdx.x] = sv[threadIdx.x];
        if (out_size >= 2 * B * KSEL)
            out[B * KSEL + q * KSEL + threadIdx.x] = (float)si[threadIdx.x];
    }
}

// ---------------------------------------------------------------------------
extern "C" void kernel_launch(void* const* d_in, const int* in_sizes, int n_in,
                              void* d_out, int out_size) {
    const float* Q = (const float*)d_in[0];   // [B, 768] fp32
    const float* E = (const float*)d_in[1];   // [N, 768] fp32
    const int B = in_sizes[0] / DDIM;         // 256
    const int N = in_sizes[1] / DDIM;         // 500000
    float* out = (float*)d_out;

    qnorm_kernel<<<(B + 7) / 8, 256>>>(Q, B);
    gemm_kernel<<<(N + TILE_N - 1) / TILE_N, 256>>>(Q, E, N);
    topk_kernel<<<B, 256>>>(out, N, B, out_size);
}

// round 4
// speedup vs baseline: 2.2895x; 2.2895x over previous
#include <cuda_runtime.h>
#include <cuda_bf16.h>
#include <cstdint>
#include <math.h>
#include <float.h>

// Retriever: B=256 queries x N=500000 embeddings, D=768, top-17 cosine.
// Pipeline: fp32->bf16 convert(+norms) -> mma.sync bf16 GEMM (HMMA) ->
//           coarse top-64 -> exact fp32 rescore -> exact top-17.
// NOTE: tcgen05 is unavailable (harness PTX targets compute_103 base).

#define DDIM   768
#define KSEL   17
#define BQ     256
#define TN     128            // embeddings per CTA tile
#define QT     128            // queries per CTA tile
#define KCH    32             // K per pipeline chunk
#define NCHUNK (DDIM / KCH)   // 24
#define NCAND  64
#define NMAX   500000
#define NPADMAX (((NMAX + TN - 1) / TN) * TN)    // 500096

// ------------------------- device scratch ----------------------------------
__device__ __nv_bfloat16 g_ebf[(size_t)NMAX * DDIM];     // 768 MB
__device__ __nv_bfloat16 g_qbf[(size_t)BQ * DDIM];
__device__ float g_inve[NMAX];
__device__ float g_invq[BQ];
__device__ float g_scores[(size_t)BQ * NPADMAX];         // ~512 MB
__device__ float g_cand_v[BQ * NCAND];
__device__ int   g_cand_i[BQ * NCAND];

// ------------------------- helpers -----------------------------------------
__device__ __forceinline__ uint32_t smem_u32(const void* p) {
    uint32_t a;
    asm("{ .reg .u64 t; cvta.to.shared.u64 t, %1; cvt.u32.u64 %0, t; }" : "=r"(a) : "l"(p));
    return a;
}
__device__ __forceinline__ void cp16(uint32_t dst, const void* src) {
    asm volatile("cp.async.cg.shared.global [%0], [%1], 16;" :: "r"(dst), "l"(src));
}
#define CP_COMMIT() asm volatile("cp.async.commit_group;" ::: "memory")
#define CP_WAIT1()  asm volatile("cp.async.wait_group 1;" ::: "memory")

__device__ __forceinline__ void mma16816(float* c, const uint32_t* a, const uint32_t* b) {
    asm volatile(
        "mma.sync.aligned.m16n8k16.row.col.f32.bf16.bf16.f32 "
        "{%0,%1,%2,%3}, {%4,%5,%6,%7}, {%8,%9}, {%0,%1,%2,%3};"
        : "+f"(c[0]), "+f"(c[1]), "+f"(c[2]), "+f"(c[3])
        : "r"(a[0]), "r"(a[1]), "r"(a[2]), "r"(a[3]), "r"(b[0]), "r"(b[1]));
}

// ===========================================================================
// Kernel 1: fp32 -> bf16 + inverse norms. One warp per row.
// ===========================================================================
__global__ void convert_kernel(const float* __restrict__ in,
                               __nv_bfloat16* __restrict__ obf,
                               float* __restrict__ invn, int rows) {
    int warp = (blockIdx.x * blockDim.x + threadIdx.x) >> 5;
    int lane = threadIdx.x & 31;
    if (warp >= rows) return;
    const float4* src = (const float4*)(in + (size_t)warp * DDIM);
    __nv_bfloat162* dst = (__nv_bfloat162*)(obf + (size_t)warp * DDIM);
    float s = 0.f;
    #pragma unroll
    for (int j = 0; j < 6; j++) {
        float4 v = src[j * 32 + lane];
        s += v.x * v.x + v.y * v.y + v.z * v.z + v.w * v.w;
        dst[(j * 32 + lane) * 2 + 0] = __floats2bfloat162_rn(v.x, v.y);
        dst[(j * 32 + lane) * 2 + 1] = __floats2bfloat162_rn(v.z, v.w);
    }
    #pragma unroll
    for (int o = 16; o; o >>= 1) s += __shfl_xor_sync(0xFFFFFFFFu, s, o);
    if (lane == 0) invn[warp] = 1.0f / sqrtf(s);
}

// ===========================================================================
// Kernel 2: bf16 mma.sync GEMM. CTA 128q x 128n, warp 32x64, K chunks of 32.
// Smem rows padded to 40 bf16 (80B) -> conflict-free fragment loads.
// ===========================================================================
#define ROWB 80                     // bytes per smem row (32 bf16 + 8 pad)
#define STAGE_B (128 * ROWB)        // 10240 bytes per operand stage

__global__ void __launch_bounds__(256, 2)
gemm_kernel(int N, int Npad) {
    __shared__ __align__(16) char sA[2 * STAGE_B];
    __shared__ __align__(16) char sB[2 * STAGE_B];
    const uint32_t aBase = smem_u32(sA);
    const uint32_t bBase = smem_u32(sB);

    const int tid  = threadIdx.x;
    const int wid  = tid >> 5;
    const int lane = tid & 31;
    const int g    = lane >> 2;      // 0..7
    const int tg   = lane & 3;       // 0..3

    const int nbase = blockIdx.x * TN;
    const int qbase = blockIdx.y * QT;
    const int wm = wid & 3;          // 4 m-warps
    const int wn = wid >> 2;         // 2 n-warps
    const int m0w = wm * 32;
    const int n0w = wn * 64;

    const char* eb = (const char*)g_ebf;
    const char* qb = (const char*)g_qbf + (size_t)qbase * (DDIM * 2);

    // chunk loader: 32-k chunk c into stage s (A: 128x64B, B: 128x64B)
    const int row2 = tid >> 1;             // 0..127
    const int segA = (tid & 1) * 2;        // {0,2} -> two 16B segs each
    auto load_chunk = [&](int c, int s) {
        const int cb = c * (KCH * 2);      // byte offset in a 1536B row
        const size_t erow = (size_t)min(nbase + row2, N - 1) * (DDIM * 2);
        #pragma unroll
        for (int j = 0; j < 2; j++) {
            int seg = segA + j;
            cp16(aBase + s * STAGE_B + row2 * ROWB + seg * 16,
                 qb + (size_t)row2 * (DDIM * 2) + cb + seg * 16);
            cp16(bBase + s * STAGE_B + row2 * ROWB + seg * 16,
                 eb + erow + cb + seg * 16);
        }
        CP_COMMIT();
    };

    load_chunk(0, 0);
    load_chunk(1, 1);

    float acc[2][8][4];
    #pragma unroll
    for (int mf = 0; mf < 2; mf++)
        #pragma unroll
        for (int nf = 0; nf < 8; nf++)
            #pragma unroll
            for (int j = 0; j < 4; j++) acc[mf][nf][j] = 0.f;

    for (int c = 0; c < NCHUNK; c++) {
        const int s = c & 1;
        CP_WAIT1();
        __syncthreads();
        const uint32_t aS = aBase + s * STAGE_B;
        const uint32_t bS = bBase + s * STAGE_B;
        #pragma unroll
        for (int kk = 0; kk < 2; kk++) {
            const int kb = kk * 32 + tg * 4;      // byte offset of 2-bf16 pair
            uint32_t a[2][4], b[8][2];
            #pragma unroll
            for (int mf = 0; mf < 2; mf++) {
                const uint32_t r0 = aS + (m0w + mf * 16 + g) * ROWB + kb;
                const uint32_t r1 = r0 + 8 * ROWB;
                asm volatile("ld.shared.b32 %0, [%1];" : "=r"(a[mf][0]) : "r"(r0));
                asm volatile("ld.shared.b32 %0, [%1];" : "=r"(a[mf][1]) : "r"(r1));
                asm volatile("ld.shared.b32 %0, [%1];" : "=r"(a[mf][2]) : "r"(r0 + 16));
                asm volatile("ld.shared.b32 %0, [%1];" : "=r"(a[mf][3]) : "r"(r1 + 16));
            }
            #pragma unroll
            for (int nf = 0; nf < 8; nf++) {
                const uint32_t rb = bS + (n0w + nf * 8 + g) * ROWB + kb;
                asm volatile("ld.shared.b32 %0, [%1];" : "=r"(b[nf][0]) : "r"(rb));
                asm volatile("ld.shared.b32 %0, [%1];" : "=r"(b[nf][1]) : "r"(rb + 16));
            }
            #pragma unroll
            for (int mf = 0; mf < 2; mf++)
                #pragma unroll
                for (int nf = 0; nf < 8; nf++)
                    mma16816(acc[mf][nf], a[mf], b[nf]);
        }
        __syncthreads();
        if (c + 2 < NCHUNK) load_chunk(c + 2, s);
    }

    // ---- epilogue: scale by invq*inve, write scores ------------------------
    float2 ie[8];
    #pragma unroll
    for (int nf = 0; nf < 8; nf++) {
        const int n = nbase + n0w + nf * 8 + 2 * tg;
        ie[nf].x = (n     < N) ? g_inve[n]     : 0.f;
        ie[nf].y = (n + 1 < N) ? g_inve[n + 1] : 0.f;
    }
    #pragma unroll
    for (int mf = 0; mf < 2; mf++) {
        #pragma unroll
        for (int h = 0; h < 2; h++) {
            const int q = qbase + m0w + mf * 16 + h * 8 + g;
            const float iq = g_invq[q];
            float* orow = g_scores + (size_t)q * Npad + nbase + n0w + 2 * tg;
            #pragma unroll
            for (int nf = 0; nf < 8; nf++) {
                const int n = nbase + n0w + nf * 8 + 2 * tg;
                float2 o;
                o.x = (n     < N) ? acc[mf][nf][2 * h]     * iq * ie[nf].x : -FLT_MAX;
                o.y = (n + 1 < N) ? acc[mf][nf][2 * h + 1] * iq * ie[nf].y : -FLT_MAX;
                *(float2*)(orow + nf * 8) = o;
            }
        }
    }
}

// ===========================================================================
// Kernel 3: coarse top-64 per query (one CTA of 256 threads per query).
// ===========================================================================
#define LK 16
__global__ void topk64_kernel(int Npad) {
    extern __shared__ char sm[];
    float* sv = (float*)sm;                 // 256*64
    int*   si = (int*)(sm + 256 * 64 * 4);  // 256*64
    const int q = blockIdx.x;
    const int tid = threadIdx.x;
    const float* row = g_scores + (size_t)q * Npad;

    float lv[LK]; int li[LK];
    #pragma unroll
    for (int j = 0; j < LK; j++) { lv[j] = -FLT_MAX; li[j] = 0x7FFFFFFF; }
    float vmin = -FLT_MAX;
    for (int n = tid; n < Npad; n += 256) {
        float v = row[n];
        if (v > vmin) {
            int pos = LK - 1;
            #pragma unroll
            for (int s = 0; s < LK - 1; s++) {
                if (pos > 0 && v > lv[pos - 1]) { lv[pos] = lv[pos-1]; li[pos] = li[pos-1]; pos--; }
            }
            lv[pos] = v; li[pos] = n;
            vmin = lv[LK - 1];
        }
    }
    #pragma unroll
    for (int j = 0; j < LK; j++) { sv[tid * 64 + j] = lv[j]; si[tid * 64 + j] = li[j]; }
    #pragma unroll
    for (int j = LK; j < 64; j++) { sv[tid * 64 + j] = -FLT_MAX; si[tid * 64 + j] = 0x7FFFFFFF; }

    int len = LK;
    for (int half = 128; half >= 1; half >>= 1) {
        int outlen = min(2 * len, 64);
        __syncthreads();
        if (tid < half) {
            float* av = &sv[tid * 64];            int* ai = &si[tid * 64];
            float* bv = &sv[(tid + half) * 64];   int* bi = &si[(tid + half) * 64];
            float tv[64]; int ti[64];
            int ia = 0, ib = 0;
            for (int j = 0; j < outlen; j++) {
                float va = (ia < len) ? av[ia] : -FLT_MAX;
                float vb = (ib < len) ? bv[ib] : -FLT_MAX;
                int xa = (ia < len) ? ai[ia] : 0x7FFFFFFF;
                int xb = (ib < len) ? bi[ib] : 0x7FFFFFFF;
                bool ta = (va > vb) || (va == vb && xa < xb);
                if (ta) { tv[j] = va; ti[j] = xa; ia++; }
                else    { tv[j] = vb; ti[j] = xb; ib++; }
            }
            for (int j = 0; j < outlen; j++) { av[j] = tv[j]; ai[j] = ti[j]; }
        }
        len = outlen;
    }
    __syncthreads();
    if (tid < NCAND) {
        g_cand_v[q * NCAND + tid] = sv[tid];
        g_cand_i[q * NCAND + tid] = si[tid];
    }
}

// ===========================================================================
// Kernel 4: exact fp32 rescore of 64 candidates + exact top-17.
// ===========================================================================
__global__ void rescore_kernel(const float* __restrict__ Q, const float* __restrict__ E,
                               float* __restrict__ out, int N, int out_size) {
    __shared__ float qs[DDIM];
    __shared__ float cv[NCAND];
    __shared__ int   ci[NCAND];
    const int q = blockIdx.x;
    const int tid = threadIdx.x;
    const int wid = tid >> 5, lane = tid & 31;

    #pragma unroll
    for (int j = 0; j < 3; j++) qs[tid + j * 256] = Q[(size_t)q * DDIM + tid + j * 256];
    __syncthreads();

    const float iq = g_invq[q];
    for (int c = wid; c < NCAND; c += 8) {
        int idx = g_cand_i[q * NCAND + c];
        int safe = (idx >= 0 && idx < N) ? idx : 0;
        const float* er = E + (size_t)safe * DDIM;
        float dot = 0.f, ss = 0.f;
        #pragma unroll
        for (int j = 0; j < 24; j++) {
            float e = er[j * 32 + lane];
            dot += qs[j * 32 + lane] * e;
            ss  += e * e;
        }
        #pragma unroll
        for (int o = 16; o; o >>= 1) {
            dot += __shfl_xor_sync(0xFFFFFFFFu, dot, o);
            ss  += __shfl_xor_sync(0xFFFFFFFFu, ss, o);
        }
        if (lane == 0) {
            cv[c] = dot * iq * (1.0f / sqrtf(ss));
            ci[c] = safe;
        }
    }
    __syncthreads();

    if (tid == 0) {
        float bv[KSEL]; int bi[KSEL];
        #pragma unroll
        for (int j = 0; j < KSEL; j++) { bv[j] = -FLT_MAX; bi[j] = 0x7FFFFFFF; }
        for (int c = 0; c < NCAND; c++) {
            float v = cv[c]; int ix = ci[c];
            bool better = (v > bv[KSEL-1]) || (v == bv[KSEL-1] && ix < bi[KSEL-1]);
            if (better) {
                int pos = KSEL - 1;
                while (pos > 0 && ((v > bv[pos-1]) || (v == bv[pos-1] && ix < bi[pos-1]))) {
                    bv[pos] = bv[pos-1]; bi[pos] = bi[pos-1]; pos--;
                }
                bv[pos] = v; bi[pos] = ix;
            }
        }
        for (int j = 0; j < KSEL; j++) {
            out[q * KSEL + j] = bv[j];
            if (out_size >= 2 * BQ * KSEL)
                out[BQ * KSEL + q * KSEL + j] = (float)bi[j];
        }
    }
}

// ===========================================================================
extern "C" void kernel_launch(void* const* d_in, const int* in_sizes, int n_in,
                              void* d_out, int out_size) {
    const float* Q = (const float*)d_in[0];
    const float* E = (const float*)d_in[1];
    const int B = in_sizes[0] / DDIM;                 // 256
    const int N = in_sizes[1] / DDIM;                 // 500000
    const int ntiles = (N + TN - 1) / TN;             // 3907
    const int Npad = ntiles * TN;                     // 500096
    float* out = (float*)d_out;

    static bool init_done = false;
    if (!init_done) {
        cudaFuncSetAttribute(topk64_kernel, cudaFuncAttributeMaxDynamicSharedMemorySize, 256 * 64 * 8);
        init_done = true;
    }
    __nv_bfloat16 *qbf_p, *ebf_p; float *invq_p, *inve_p;
    cudaGetSymbolAddress((void**)&qbf_p, g_qbf);
    cudaGetSymbolAddress((void**)&ebf_p, g_ebf);
    cudaGetSymbolAddress((void**)&invq_p, g_invq);
    cudaGetSymbolAddress((void**)&inve_p, g_inve);

    convert_kernel<<<(B + 7) / 8, 256>>>(Q, qbf_p, invq_p, B);
    convert_kernel<<<(N + 7) / 8, 256>>>(E, ebf_p, inve_p, N);
    dim3 ggrid(ntiles, (B + QT - 1) / QT);
    gemm_kernel<<<ggrid, 256>>>(N, Npad);
    topk64_kernel<<<B, 256, 256 * 64 * 8>>>(Npad);
    rescore_kernel<<<B, 256>>>(Q, E, out, N, out_size);
}

// round 5
// speedup vs baseline: 2.3357x; 1.0202x over previous
#include <cuda_runtime.h>
#include <cuda_bf16.h>
#include <cstdint>
#include <math.h>
#include <float.h>

// Retriever: B=256 x N=500000, D=768, top-17 cosine.
// convert(+norms) -> bf16 mma.sync GEMM (ldmatrix, warp 64x64) ->
// coarse top-64 -> exact fp32 rescore -> exact top-17.

#define DDIM   768
#define KSEL   17
#define BQ     256
#define TN     256            // embeddings per CTA tile
#define QT     128            // queries per CTA tile
#define KCH    32             // K per pipeline chunk
#define NCHUNK (DDIM / KCH)   // 24
#define NSTG   3
#define NCAND  64
#define NMAX   500000
#define NPADMAX (((NMAX + TN - 1) / TN) * TN)    // 500224

#define ROWB    80                 // 64B data + 16B pad (LDSM conflict-free)
#define A_STAGE (QT * ROWB)        // 10240
#define B_STAGE (TN * ROWB)        // 20480
#define SM_GEMM (NSTG * (A_STAGE + B_STAGE))   // 92160

// ------------------------- device scratch ----------------------------------
__device__ __nv_bfloat16 g_ebf[(size_t)NMAX * DDIM];
__device__ __nv_bfloat16 g_qbf[(size_t)BQ * DDIM];
__device__ float g_inve[NMAX];
__device__ float g_invq[BQ];
__device__ float g_scores[(size_t)BQ * NPADMAX];
__device__ float g_cand_v[BQ * NCAND];
__device__ int   g_cand_i[BQ * NCAND];

// ------------------------- helpers -----------------------------------------
__device__ __forceinline__ uint32_t smem_u32(const void* p) {
    uint32_t a;
    asm("{ .reg .u64 t; cvta.to.shared.u64 t, %1; cvt.u32.u64 %0, t; }" : "=r"(a) : "l"(p));
    return a;
}
__device__ __forceinline__ void cp16(uint32_t dst, const void* src) {
    asm volatile("cp.async.cg.shared.global [%0], [%1], 16;" :: "r"(dst), "l"(src));
}
#define CP_COMMIT() asm volatile("cp.async.commit_group;" ::: "memory")
#define CP_WAIT2()  asm volatile("cp.async.wait_group 2;" ::: "memory")

__device__ __forceinline__ void ldsm4(uint32_t* r, uint32_t addr) {
    asm volatile("ldmatrix.sync.aligned.m8n8.x4.shared.b16 {%0,%1,%2,%3}, [%4];"
                 : "=r"(r[0]), "=r"(r[1]), "=r"(r[2]), "=r"(r[3]) : "r"(addr));
}
__device__ __forceinline__ void mma16816(float* c, const uint32_t* a, uint32_t b0, uint32_t b1) {
    asm volatile(
        "mma.sync.aligned.m16n8k16.row.col.f32.bf16.bf16.f32 "
        "{%0,%1,%2,%3}, {%4,%5,%6,%7}, {%8,%9}, {%0,%1,%2,%3};"
        : "+f"(c[0]), "+f"(c[1]), "+f"(c[2]), "+f"(c[3])
        : "r"(a[0]), "r"(a[1]), "r"(a[2]), "r"(a[3]), "r"(b0), "r"(b1));
}

// ===========================================================================
// Kernel 1: fp32 -> bf16 + inverse norms. One warp per row.
// ===========================================================================
__global__ void convert_kernel(const float* __restrict__ in,
                               __nv_bfloat16* __restrict__ obf,
                               float* __restrict__ invn, int rows) {
    int warp = (blockIdx.x * blockDim.x + threadIdx.x) >> 5;
    int lane = threadIdx.x & 31;
    if (warp >= rows) return;
    const float4* src = (const float4*)(in + (size_t)warp * DDIM);
    __nv_bfloat162* dst = (__nv_bfloat162*)(obf + (size_t)warp * DDIM);
    float s = 0.f;
    #pragma unroll
    for (int j = 0; j < 6; j++) {
        float4 v = src[j * 32 + lane];
        s += v.x * v.x + v.y * v.y + v.z * v.z + v.w * v.w;
        dst[(j * 32 + lane) * 2 + 0] = __floats2bfloat162_rn(v.x, v.y);
        dst[(j * 32 + lane) * 2 + 1] = __floats2bfloat162_rn(v.z, v.w);
    }
    #pragma unroll
    for (int o = 16; o; o >>= 1) s += __shfl_xor_sync(0xFFFFFFFFu, s, o);
    if (lane == 0) invn[warp] = 1.0f / sqrtf(s);
}

// ===========================================================================
// Kernel 2: bf16 mma.sync GEMM. CTA 128q x 256n, warp 64x64, 3-stage pipeline.
// grid = (2 qtiles, 1954 ntiles): adjacent CTAs share the E tile in L2.
// ===========================================================================
__global__ void __launch_bounds__(256, 1)
gemm_kernel(int N, int Npad) {
    extern __shared__ __align__(16) char smem[];
    const uint32_t smBase = smem_u32(smem);

    const int tid  = threadIdx.x;
    const int wid  = tid >> 5;
    const int lane = tid & 31;
    const int g    = lane >> 2;
    const int tg   = lane & 3;

    const int qbase = blockIdx.x * QT;
    const int nbase = blockIdx.y * TN;
    const int m0w = (wid & 1) * 64;     // 2 m-warps
    const int n0w = (wid >> 1) * 64;    // 4 n-warps

    // ldmatrix per-lane offsets
    const int sel = lane >> 3, r8 = lane & 7;
    const uint32_t aOff = (uint32_t)((m0w + (sel & 1) * 8 + r8) * ROWB + (sel >> 1) * 16);
    const uint32_t bOff = (uint32_t)((n0w + (sel >> 1) * 8 + r8) * ROWB + (sel & 1) * 16);

    const char* eb = (const char*)g_ebf;
    const char* qb = (const char*)g_qbf + (size_t)qbase * (DDIM * 2);

    // loader: A 128 rows x 4 segs, B 256 rows x 4 segs (16B each)
    auto load_chunk = [&](int c, int s) {
        const int cb = c * (KCH * 2);
        const uint32_t aS = smBase + s * A_STAGE;
        const uint32_t bS = smBase + NSTG * A_STAGE + s * B_STAGE;
        #pragma unroll
        for (int i = 0; i < 2; i++) {
            int idx = tid + i * 256, row = idx >> 2, seg = idx & 3;
            cp16(aS + row * ROWB + seg * 16,
                 qb + (size_t)row * (DDIM * 2) + cb + seg * 16);
        }
        #pragma unroll
        for (int i = 0; i < 4; i++) {
            int idx = tid + i * 256, row = idx >> 2, seg = idx & 3;
            int grow = nbase + row; if (grow >= N) grow = N - 1;
            cp16(bS + row * ROWB + seg * 16,
                 eb + (size_t)grow * (DDIM * 2) + cb + seg * 16);
        }
        CP_COMMIT();
    };

    load_chunk(0, 0);
    load_chunk(1, 1);
    load_chunk(2, 2);

    float acc[4][8][4];
    #pragma unroll
    for (int mf = 0; mf < 4; mf++)
        #pragma unroll
        for (int nf = 0; nf < 8; nf++)
            #pragma unroll
            for (int j = 0; j < 4; j++) acc[mf][nf][j] = 0.f;

    int s = 0;
    for (int c = 0; c < NCHUNK; c++) {
        CP_WAIT2();                        // group c complete
        __syncthreads();
        const uint32_t aS = smBase + s * A_STAGE + aOff;
        const uint32_t bS = smBase + NSTG * A_STAGE + s * B_STAGE + bOff;
        #pragma unroll
        for (int kk = 0; kk < 2; kk++) {
            uint32_t a[4][4], b[4][4];
            #pragma unroll
            for (int mf = 0; mf < 4; mf++) ldsm4(a[mf], aS + mf * (16 * ROWB) + kk * 32);
            #pragma unroll
            for (int p = 0; p < 4; p++)    ldsm4(b[p], bS + p * (16 * ROWB) + kk * 32);
            #pragma unroll
            for (int mf = 0; mf < 4; mf++)
                #pragma unroll
                for (int nf = 0; nf < 8; nf++)
                    mma16816(acc[mf][nf], a[mf], b[nf >> 1][(nf & 1) * 2], b[nf >> 1][(nf & 1) * 2 + 1]);
        }
        __syncthreads();
        if (c + NSTG < NCHUNK) load_chunk(c + NSTG, s);
        else CP_COMMIT();                  // keep group count uniform
        s = (s + 1 == NSTG) ? 0 : s + 1;
    }

    // ---- epilogue ----------------------------------------------------------
    float2 ie[8];
    #pragma unroll
    for (int nf = 0; nf < 8; nf++) {
        const int n = nbase + n0w + nf * 8 + 2 * tg;
        ie[nf].x = (n     < N) ? g_inve[n]     : 0.f;
        ie[nf].y = (n + 1 < N) ? g_inve[n + 1] : 0.f;
    }
    #pragma unroll
    for (int mf = 0; mf < 4; mf++) {
        #pragma unroll
        for (int h = 0; h < 2; h++) {
            const int q = qbase + m0w + mf * 16 + h * 8 + g;
            const float iq = g_invq[q];
            float* orow = g_scores + (size_t)q * Npad + nbase + n0w + 2 * tg;
            #pragma unroll
            for (int nf = 0; nf < 8; nf++) {
                const int n = nbase + n0w + nf * 8 + 2 * tg;
                float2 o;
                o.x = (n     < N) ? acc[mf][nf][2 * h]     * iq * ie[nf].x : -FLT_MAX;
                o.y = (n + 1 < N) ? acc[mf][nf][2 * h + 1] * iq * ie[nf].y : -FLT_MAX;
                *(float2*)(orow + nf * 8) = o;
            }
        }
    }
}

// ===========================================================================
// Kernel 3: coarse top-64 per query.
// ===========================================================================
#define LK 16
__global__ void topk64_kernel(int Npad) {
    extern __shared__ char sm[];
    float* sv = (float*)sm;
    int*   si = (int*)(sm + 256 * 64 * 4);
    const int q = blockIdx.x;
    const int tid = threadIdx.x;
    const float* row = g_scores + (size_t)q * Npad;

    float lv[LK]; int li[LK];
    #pragma unroll
    for (int j = 0; j < LK; j++) { lv[j] = -FLT_MAX; li[j] = 0x7FFFFFFF; }
    float vmin = -FLT_MAX;
    for (int n = tid; n < Npad; n += 256) {
        float v = row[n];
        if (v > vmin) {
            int pos = LK - 1;
            #pragma unroll
            for (int st = 0; st < LK - 1; st++) {
                if (pos > 0 && v > lv[pos - 1]) { lv[pos] = lv[pos-1]; li[pos] = li[pos-1]; pos--; }
            }
            lv[pos] = v; li[pos] = n;
            vmin = lv[LK - 1];
        }
    }
    #pragma unroll
    for (int j = 0; j < LK; j++) { sv[tid * 64 + j] = lv[j]; si[tid * 64 + j] = li[j]; }
    #pragma unroll
    for (int j = LK; j < 64; j++) { sv[tid * 64 + j] = -FLT_MAX; si[tid * 64 + j] = 0x7FFFFFFF; }

    int len = LK;
    for (int half = 128; half >= 1; half >>= 1) {
        int outlen = min(2 * len, 64);
        __syncthreads();
        if (tid < half) {
            float* av = &sv[tid * 64];            int* ai = &si[tid * 64];
            float* bv = &sv[(tid + half) * 64];   int* bi = &si[(tid + half) * 64];
            float tv[64]; int ti[64];
            int ia = 0, ib = 0;
            for (int j = 0; j < outlen; j++) {
                float va = (ia < len) ? av[ia] : -FLT_MAX;
                float vb = (ib < len) ? bv[ib] : -FLT_MAX;
                int xa = (ia < len) ? ai[ia] : 0x7FFFFFFF;
                int xb = (ib < len) ? bi[ib] : 0x7FFFFFFF;
                bool ta = (va > vb) || (va == vb && xa < xb);
                if (ta) { tv[j] = va; ti[j] = xa; ia++; }
                else    { tv[j] = vb; ti[j] = xb; ib++; }
            }
            for (int j = 0; j < outlen; j++) { av[j] = tv[j]; ai[j] = ti[j]; }
        }
        len = outlen;
    }
    __syncthreads();
    if (tid < NCAND) {
        g_cand_v[q * NCAND + tid] = sv[tid];
        g_cand_i[q * NCAND + tid] = si[tid];
    }
}

// ===========================================================================
// Kernel 4: exact fp32 rescore of 64 candidates + exact top-17.
// ===========================================================================
__global__ void rescore_kernel(const float* __restrict__ Q, const float* __restrict__ E,
                               float* __restrict__ out, int N, int out_size) {
    __shared__ float qs[DDIM];
    __shared__ float cv[NCAND];
    __shared__ int   ci[NCAND];
    const int q = blockIdx.x;
    const int tid = threadIdx.x;
    const int wid = tid >> 5, lane = tid & 31;

    #pragma unroll
    for (int j = 0; j < 3; j++) qs[tid + j * 256] = Q[(size_t)q * DDIM + tid + j * 256];
    __syncthreads();

    const float iq = g_invq[q];
    for (int c = wid; c < NCAND; c += 8) {
        int idx = g_cand_i[q * NCAND + c];
        int safe = (idx >= 0 && idx < N) ? idx : 0;
        const float* er = E + (size_t)safe * DDIM;
        float dot = 0.f, ss = 0.f;
        #pragma unroll
        for (int j = 0; j < 24; j++) {
            float e = er[j * 32 + lane];
            dot += qs[j * 32 + lane] * e;
            ss  += e * e;
        }
        #pragma unroll
        for (int o = 16; o; o >>= 1) {
            dot += __shfl_xor_sync(0xFFFFFFFFu, dot, o);
            ss  += __shfl_xor_sync(0xFFFFFFFFu, ss, o);
        }
        if (lane == 0) {
            cv[c] = dot * iq * (1.0f / sqrtf(ss));
            ci[c] = safe;
        }
    }
    __syncthreads();

    if (tid == 0) {
        float bv[KSEL]; int bi[KSEL];
        #pragma unroll
        for (int j = 0; j < KSEL; j++) { bv[j] = -FLT_MAX; bi[j] = 0x7FFFFFFF; }
        for (int c = 0; c < NCAND; c++) {
            float v = cv[c]; int ix = ci[c];
            bool better = (v > bv[KSEL-1]) || (v == bv[KSEL-1] && ix < bi[KSEL-1]);
            if (better) {
                int pos = KSEL - 1;
                while (pos > 0 && ((v > bv[pos-1]) || (v == bv[pos-1] && ix < bi[pos-1]))) {
                    bv[pos] = bv[pos-1]; bi[pos] = bi[pos-1]; pos--;
                }
                bv[pos] = v; bi[pos] = ix;
            }
        }
        for (int j = 0; j < KSEL; j++) {
            out[q * KSEL + j] = bv[j];
            if (out_size >= 2 * BQ * KSEL)
                out[BQ * KSEL + q * KSEL + j] = (float)bi[j];
        }
    }
}

// ===========================================================================
extern "C" void kernel_launch(void* const* d_in, const int* in_sizes, int n_in,
                              void* d_out, int out_size) {
    const float* Q = (const float*)d_in[0];
    const float* E = (const float*)d_in[1];
    const int B = in_sizes[0] / DDIM;
    const int N = in_sizes[1] / DDIM;
    const int ntiles = (N + TN - 1) / TN;             // 1954
    const int Npad = ntiles * TN;                     // 500224
    float* out = (float*)d_out;

    static bool init_done = false;
    if (!init_done) {
        cudaFuncSetAttribute(gemm_kernel, cudaFuncAttributeMaxDynamicSharedMemorySize, SM_GEMM);
        cudaFuncSetAttribute(topk64_kernel, cudaFuncAttributeMaxDynamicSharedMemorySize, 256 * 64 * 8);
        init_done = true;
    }
    __nv_bfloat16 *qbf_p, *ebf_p; float *invq_p, *inve_p;
    cudaGetSymbolAddress((void**)&qbf_p, g_qbf);
    cudaGetSymbolAddress((void**)&ebf_p, g_ebf);
    cudaGetSymbolAddress((void**)&invq_p, g_invq);
    cudaGetSymbolAddress((void**)&inve_p, g_inve);

    convert_kernel<<<(B + 7) / 8, 256>>>(Q, qbf_p, invq_p, B);
    convert_kernel<<<(N + 7) / 8, 256>>>(E, ebf_p, inve_p, N);
    dim3 ggrid((B + QT - 1) / QT, ntiles);            // (2, 1954)
    gemm_kernel<<<ggrid, 256, SM_GEMM>>>(N, Npad);
    topk64_kernel<<<B, 256, 256 * 64 * 8>>>(Npad);
    rescore_kernel<<<B, 256>>>(Q, E, out, N, out_size);
}